// round 1
// baseline (speedup 1.0000x reference)
#include <cuda_runtime.h>
#include <cstdint>

// Problem constants (from reference)
namespace {
constexpr int kB   = 256;   // batch
constexpr int kD   = 2048;  // latent dim (K)
constexpr int kS   = 8;     // subjects
constexpr int kOut = 1000;  // output dim (N)

constexpr int BM = 32;      // rows per block tile
constexpr int BN = 64;      // cols per block tile
constexpr int BK = 16;      // K per stage
}

// Device scratch (no allocations allowed in kernel_launch)
__device__ int g_counts[kS];
__device__ int g_rows[kS * kB];

// ---------------------------------------------------------------------------
// Kernel 1: bucket rows by subject. Re-zeroes counts every launch (graph
// replays the same work). Detects int64-vs-int32 subject_ids robustly:
// for int64 (little-endian), odd 32-bit words among the first 256 words are
// the high halves of elements 0..127 and are all zero; for int32 they are
// 128 random ids in [0,8) — all-zero w.p. (1/8)^128.
// ---------------------------------------------------------------------------
__global__ void bucket_kernel(const unsigned int* __restrict__ sid_words) {
    __shared__ int is_i32;
    const int t = threadIdx.x;
    if (t == 0) is_i32 = 0;
    if (t < kS) g_counts[t] = 0;
    __syncthreads();
    if (t < 128) {
        if (sid_words[2 * t + 1] != 0u) atomicOr(&is_i32, 1);
    }
    __syncthreads();
    if (t < kB) {
        const int s = is_i32 ? (int)sid_words[t] : (int)sid_words[2 * t];
        const int p = atomicAdd(&g_counts[s], 1);
        g_rows[s * kB + p] = t;
    }
}

// ---------------------------------------------------------------------------
// Kernel 2: per-subject tiled SGEMM.
// Block = (n_tile, subject, m_tile). Most (subject, m_tile) combos are empty
// (counts ~Binomial(256,1/8) ≈ 32) and exit before touching W, so W is read
// from HBM ~exactly once in aggregate.
// 256 threads, 2x4 register tile, register-staged global->smem pipeline.
// ---------------------------------------------------------------------------
__global__ __launch_bounds__(256) void gemm_kernel(
    const float* __restrict__ x,     // [B, D]
    const float* __restrict__ W,     // [S, D, OUT]
    const float* __restrict__ bias,  // [S, OUT]
    float* __restrict__ out)         // [B, OUT]
{
    const int s   = blockIdx.y;
    const int cnt = g_counts[s];
    const int m0  = blockIdx.z * BM;
    if (m0 >= cnt) return;
    const int n0  = blockIdx.x * BN;

    __shared__ float Xs[BK][BM];   // [k][m]
    __shared__ float Ws[BK][BN];   // [k][n]
    __shared__ int   rows[BM];

    const int t = threadIdx.x;
    if (t < BM) {
        const int idx = m0 + t;
        rows[t] = (idx < cnt) ? g_rows[s * kB + idx] : -1;
    }
    __syncthreads();

    // --- global-load roles ---
    const int lm  = t & 31;            // X: row within tile
    const int lkx = t >> 5;            // X: k-slot 0..7 (loads lkx and lkx+8)
    const int xrow = rows[lm];
    const float* xptr = (xrow >= 0) ? (x + (size_t)xrow * kD) : nullptr;

    const int ln4 = (t & 15) * 4;      // W: col quad within tile
    const int lkw = t >> 4;            // W: k-row 0..15
    const float* wptr = W + ((size_t)s * kD + (size_t)lkw) * kOut + n0 + ln4;
    const bool w_full = (n0 + ln4 + 3) < kOut;

    // --- compute roles: thread covers rows [tm, tm+1], cols [tn, tn+3] ---
    const int tm = (t & 15) * 2;
    const int tn = (t >> 4) * 4;

    float acc[2][4] = {{0.f,0.f,0.f,0.f},{0.f,0.f,0.f,0.f}};

    float xr0, xr1;
    float4 wr;
    auto load_stage = [&](int k0) {
        xr0 = xptr ? __ldg(xptr + k0 + lkx)     : 0.f;
        xr1 = xptr ? __ldg(xptr + k0 + lkx + 8) : 0.f;
        const float* wp = wptr + (size_t)k0 * kOut;
        if (w_full) {
            wr = *reinterpret_cast<const float4*>(wp);
        } else {
            wr.x = (n0 + ln4 + 0 < kOut) ? wp[0] : 0.f;
            wr.y = (n0 + ln4 + 1 < kOut) ? wp[1] : 0.f;
            wr.z = (n0 + ln4 + 2 < kOut) ? wp[2] : 0.f;
            wr.w = (n0 + ln4 + 3 < kOut) ? wp[3] : 0.f;
        }
    };

    load_stage(0);
    for (int k0 = 0; k0 < kD; k0 += BK) {
        // commit staged registers to smem
        Xs[lkx][lm]     = xr0;
        Xs[lkx + 8][lm] = xr1;
        *reinterpret_cast<float4*>(&Ws[lkw][ln4]) = wr;
        __syncthreads();
        // issue next stage's global loads before computing (latency overlap)
        if (k0 + BK < kD) load_stage(k0 + BK);
        #pragma unroll
        for (int kk = 0; kk < BK; ++kk) {
            const float2 a = *reinterpret_cast<const float2*>(&Xs[kk][tm]);
            const float4 w = *reinterpret_cast<const float4*>(&Ws[kk][tn]);
            acc[0][0] = fmaf(a.x, w.x, acc[0][0]);
            acc[0][1] = fmaf(a.x, w.y, acc[0][1]);
            acc[0][2] = fmaf(a.x, w.z, acc[0][2]);
            acc[0][3] = fmaf(a.x, w.w, acc[0][3]);
            acc[1][0] = fmaf(a.y, w.x, acc[1][0]);
            acc[1][1] = fmaf(a.y, w.y, acc[1][1]);
            acc[1][2] = fmaf(a.y, w.z, acc[1][2]);
            acc[1][3] = fmaf(a.y, w.w, acc[1][3]);
        }
        __syncthreads();
    }

    // epilogue: bias + scatter to gathered rows
    #pragma unroll
    for (int i = 0; i < 2; ++i) {
        const int r = rows[tm + i];
        if (r < 0) continue;
        #pragma unroll
        for (int j = 0; j < 4; ++j) {
            const int n = n0 + tn + j;
            if (n < kOut)
                out[(size_t)r * kOut + n] = acc[i][j] + bias[s * kOut + n];
        }
    }
}

extern "C" void kernel_launch(void* const* d_in, const int* in_sizes, int n_in,
                              void* d_out, int out_size) {
    const float*        x   = (const float*)d_in[0];
    const unsigned int* sid = (const unsigned int*)d_in[1];
    const float*        W   = (const float*)d_in[2];
    const float*        b   = (const float*)d_in[3];
    float*              out = (float*)d_out;

    bucket_kernel<<<1, 256>>>(sid);
    dim3 grid((kOut + BN - 1) / BN, kS, kB / BM);  // (16, 8, 8)
    gemm_kernel<<<grid, 256>>>(x, W, b, out);
}

// round 2
// speedup vs baseline: 2.1444x; 2.1444x over previous
#include <cuda_runtime.h>
#include <cstdint>

namespace {
constexpr int kB   = 256;   // batch
constexpr int kD   = 2048;  // latent dim (K)
constexpr int kS   = 8;     // subjects
constexpr int kOut = 1000;  // output dim (N)

constexpr int BM = 32;      // rows per block tile
constexpr int BN = 128;     // cols per block tile
constexpr int BK = 16;      // K per smem stage
constexpr int NSPLIT = 8;   // split-K factor
constexpr int KSPLIT = kD / NSPLIT;   // 256
constexpr int MT = 8;       // max m-tiles per subject (covers cnt up to 256)
}

// Device scratch (allocations are forbidden in kernel_launch)
__device__ int   g_counts[kS];
__device__ int   g_rows[kS * kB];
__device__ int   g_sid[kB];
__device__ float g_partial[NSPLIT * kB * kOut];   // 8 MB

// ---------------------------------------------------------------------------
// Kernel 1: bucket rows by subject; also record sid per row for the reduce.
// int64-vs-int32 detection: for little-endian int64 ids in [0,8), all odd
// 32-bit words of the first 256 words are zero; for int32 they are 128
// random ids (all-zero w.p. 8^-128).
// ---------------------------------------------------------------------------
__global__ void bucket_kernel(const unsigned int* __restrict__ sid_words) {
    __shared__ int is_i32;
    const int t = threadIdx.x;
    if (t == 0) is_i32 = 0;
    if (t < kS) g_counts[t] = 0;
    __syncthreads();
    if (t < 128) {
        if (sid_words[2 * t + 1] != 0u) atomicOr(&is_i32, 1);
    }
    __syncthreads();
    if (t < kB) {
        const int s = is_i32 ? (int)sid_words[t] : (int)sid_words[2 * t];
        g_sid[t] = s;
        const int p = atomicAdd(&g_counts[s], 1);
        g_rows[s * kB + p] = t;
    }
}

// ---------------------------------------------------------------------------
// Kernel 2: per-subject split-K SGEMM into partial buffer.
// grid = (n_tiles=8, subjects=8, m_tiles(8) x splits(8) = 64), 128 threads.
// Thread tile 4m x 8n (32 accumulators): 32 FMA per 12 smem words.
// ---------------------------------------------------------------------------
__global__ __launch_bounds__(128) void gemm_kernel(
    const float* __restrict__ x,     // [B, D]
    const float* __restrict__ W)     // [S, D, OUT]
{
    const int s     = blockIdx.y;
    const int cnt   = g_counts[s];
    const int mt    = blockIdx.z & (MT - 1);
    const int split = blockIdx.z >> 3;
    const int m0    = mt * BM;
    if (m0 >= cnt) return;
    const int n0    = blockIdx.x * BN;
    const int kbase = split * KSPLIT;

    __shared__ float Xs[BK][BM];     // [k][m]
    __shared__ float Ws[BK][BN];     // [k][n]
    __shared__ int   rows[BM];

    const int t = threadIdx.x;
    if (t < BM) {
        const int idx = m0 + t;
        rows[t] = (idx < cnt) ? g_rows[s * kB + idx] : -1;
    }
    __syncthreads();

    // ---- global-load roles ----
    // X: thread loads float4 along k for one row: m = t&31, k quad = (t>>5)*4
    const int xm = t & 31;
    const int xk = (t >> 5) * 4;
    const int xrow = rows[xm];
    const float* xptr = (xrow >= 0) ? (x + (size_t)xrow * kD + xk) : nullptr;

    // W: thread covers col quad wn for k-rows wk, wk+4, wk+8, wk+12
    const int wn = (t & 31) * 4;
    const int wk = t >> 5;
    const float* wptr = W + ((size_t)s * kD) * kOut + n0 + wn;
    const bool w_full = (n0 + wn + 3) < kOut;

    // ---- compute roles: rows [ty*4, +4), cols [tx*8, +8) ----
    const int ty = t >> 4;   // 0..7
    const int tx = t & 15;   // 0..15
    const int tm = ty * 4;
    const int tn = tx * 8;

    float acc[4][8];
    #pragma unroll
    for (int i = 0; i < 4; ++i)
        #pragma unroll
        for (int j = 0; j < 8; ++j) acc[i][j] = 0.f;

    float4 xr;
    float4 wr[4];
    auto load_stage = [&](int k0) {
        xr = xptr ? *reinterpret_cast<const float4*>(xptr + k0)
                  : make_float4(0.f, 0.f, 0.f, 0.f);
        #pragma unroll
        for (int q = 0; q < 4; ++q) {
            const float* wp = wptr + (size_t)(k0 + wk + q * 4) * kOut;
            if (w_full) {
                wr[q] = *reinterpret_cast<const float4*>(wp);
            } else {
                wr[q].x = (n0 + wn + 0 < kOut) ? wp[0] : 0.f;
                wr[q].y = (n0 + wn + 1 < kOut) ? wp[1] : 0.f;
                wr[q].z = (n0 + wn + 2 < kOut) ? wp[2] : 0.f;
                wr[q].w = (n0 + wn + 3 < kOut) ? wp[3] : 0.f;
            }
        }
    };

    load_stage(kbase);
    for (int k0 = kbase; k0 < kbase + KSPLIT; k0 += BK) {
        // commit staged registers to smem
        Xs[xk + 0][xm] = xr.x;
        Xs[xk + 1][xm] = xr.y;
        Xs[xk + 2][xm] = xr.z;
        Xs[xk + 3][xm] = xr.w;
        #pragma unroll
        for (int q = 0; q < 4; ++q)
            *reinterpret_cast<float4*>(&Ws[wk + q * 4][wn]) = wr[q];
        __syncthreads();
        if (k0 + BK < kbase + KSPLIT) load_stage(k0 + BK);
        #pragma unroll
        for (int kk = 0; kk < BK; ++kk) {
            const float4 a  = *reinterpret_cast<const float4*>(&Xs[kk][tm]);
            const float4 w0 = *reinterpret_cast<const float4*>(&Ws[kk][tn]);
            const float4 w1 = *reinterpret_cast<const float4*>(&Ws[kk][tn + 4]);
            const float am[4] = {a.x, a.y, a.z, a.w};
            const float wv[8] = {w0.x, w0.y, w0.z, w0.w, w1.x, w1.y, w1.z, w1.w};
            #pragma unroll
            for (int i = 0; i < 4; ++i)
                #pragma unroll
                for (int j = 0; j < 8; ++j)
                    acc[i][j] = fmaf(am[i], wv[j], acc[i][j]);
        }
        __syncthreads();
    }

    // epilogue: write partials (no bias here; reduce adds it once)
    float* pbase = g_partial + (size_t)split * kB * kOut;
    #pragma unroll
    for (int i = 0; i < 4; ++i) {
        const int r = rows[tm + i];
        if (r < 0) continue;
        float* prow = pbase + (size_t)r * kOut;
        #pragma unroll
        for (int j = 0; j < 8; ++j) {
            const int n = n0 + tn + j;
            if (n < kOut) prow[n] = acc[i][j];
        }
    }
}

// ---------------------------------------------------------------------------
// Kernel 3: reduce splits + per-subject bias.
// ---------------------------------------------------------------------------
__global__ __launch_bounds__(256) void reduce_kernel(
    const float* __restrict__ bias,  // [S, OUT]
    float* __restrict__ out)         // [B, OUT]
{
    const int idx = blockIdx.x * blockDim.x + threadIdx.x;
    if (idx >= kB * kOut) return;
    const int b = idx / kOut;
    const int n = idx - b * kOut;
    float v = 0.f;
    #pragma unroll
    for (int sp = 0; sp < NSPLIT; ++sp)
        v += g_partial[(size_t)sp * kB * kOut + idx];
    out[idx] = v + bias[g_sid[b] * kOut + n];
}

extern "C" void kernel_launch(void* const* d_in, const int* in_sizes, int n_in,
                              void* d_out, int out_size) {
    const float*        x   = (const float*)d_in[0];
    const unsigned int* sid = (const unsigned int*)d_in[1];
    const float*        W   = (const float*)d_in[2];
    const float*        b   = (const float*)d_in[3];
    float*              out = (float*)d_out;

    bucket_kernel<<<1, 256>>>(sid);
    dim3 grid(kOut / BN + (kOut % BN ? 1 : 0), kS, MT * NSPLIT);  // (8, 8, 64)
    gemm_kernel<<<grid, 128>>>(x, W);
    reduce_kernel<<<(kB * kOut + 255) / 256, 256>>>(b, out);
}